// round 1
// baseline (speedup 1.0000x reference)
#include <cuda_runtime.h>
#include <math.h>

#define N_NODES 50000
#define N_EDGES 600000
#define DIM     128
#define DIM4    32          // DIM/4 float4s per row
#define NLAYER  5
#define BN_EPS  1e-5f

// ---------------- device scratch (no allocs allowed) ----------------
__device__ float g_h  [N_NODES * DIM];       // node features (input of layer)
__device__ float g_agg[N_NODES * DIM];       // aggregation result / h2 reuse
__device__ float g_mid[N_NODES * 2 * DIM];   // hidden (N x 256)
__device__ int   g_counts[N_NODES];
__device__ int   g_row[N_NODES + 1];
__device__ int   g_cursor[N_NODES];
__device__ int   g_bsums[64];
__device__ int   g_csr_src[N_EDGES];
__device__ int   g_csr_ea [N_EDGES];
__device__ float g_stats[2 * DIM];           // [0:128) sum, [128:256) sumsq

// ---------------- kernels ----------------

// h[v] = atom_emb[x0] + chir_emb[x1] + hyb_emb[x2]
__global__ void k_init_h(const int* __restrict__ x,
                         const float* __restrict__ ae,
                         const float* __restrict__ ce,
                         const float* __restrict__ he) {
    int i = blockIdx.x * blockDim.x + threadIdx.x;
    if (i >= N_NODES * DIM4) return;
    int r = i >> 5, q = i & 31;
    int a = x[r * 3 + 0];
    int c = x[r * 3 + 1];
    int h = x[r * 3 + 2];
    float4 v  = ((const float4*)ae)[a * DIM4 + q];
    float4 v2 = ((const float4*)ce)[c * DIM4 + q];
    float4 v3 = ((const float4*)he)[h * DIM4 + q];
    v.x += v2.x + v3.x; v.y += v2.y + v3.y;
    v.z += v2.z + v3.z; v.w += v2.w + v3.w;
    ((float4*)g_h)[i] = v;
}

__global__ void k_zero_counts() {
    int i = blockIdx.x * blockDim.x + threadIdx.x;
    if (i < N_NODES) g_counts[i] = 0;
}

__global__ void k_hist(const int* __restrict__ ei) {
    int e = blockIdx.x * blockDim.x + threadIdx.x;
    if (e >= N_EDGES) return;
    atomicAdd(&g_counts[ei[N_EDGES + e]], 1);   // dst row
}

// per-block exclusive scan of counts -> g_row[0..N), block totals -> g_bsums
__global__ void k_scan1() {
    __shared__ int sm[1024];
    int t = threadIdx.x;
    int gid = blockIdx.x * 1024 + t;
    int v = (gid < N_NODES) ? g_counts[gid] : 0;
    sm[t] = v;
    __syncthreads();
    for (int off = 1; off < 1024; off <<= 1) {
        int add = (t >= off) ? sm[t - off] : 0;
        __syncthreads();
        sm[t] += add;
        __syncthreads();
    }
    if (gid < N_NODES) g_row[gid] = sm[t] - v;   // exclusive within block
    if (t == 1023) g_bsums[blockIdx.x] = sm[1023];
}

// exclusive scan of the 49 block sums (single block of 64 threads)
__global__ void k_scan2(int nb) {
    __shared__ int sm[64];
    int t = threadIdx.x;
    int v = (t < nb) ? g_bsums[t] : 0;
    sm[t] = v;
    __syncthreads();
    for (int off = 1; off < 64; off <<= 1) {
        int add = (t >= off) ? sm[t - off] : 0;
        __syncthreads();
        sm[t] += add;
        __syncthreads();
    }
    if (t < nb) g_bsums[t] = sm[t] - v;          // exclusive
}

__global__ void k_scan3() {
    int gid = blockIdx.x * blockDim.x + threadIdx.x;
    if (gid < N_NODES) {
        int r = g_row[gid] + g_bsums[gid >> 10];
        g_row[gid] = r;
        g_cursor[gid] = r;
    }
    if (gid == 0) g_row[N_NODES] = N_EDGES;
}

__global__ void k_scatter(const int* __restrict__ ei, const int* __restrict__ ea) {
    int e = blockIdx.x * blockDim.x + threadIdx.x;
    if (e >= N_EDGES) return;
    int d = ei[N_EDGES + e];
    int p = atomicAdd(&g_cursor[d], 1);
    g_csr_src[p] = ei[e];
    g_csr_ea[p]  = ea[2 * e] + (ea[2 * e + 1] << 3);
}

// one warp per node: agg[v] = sum_{e in CSR(v)} (h[src(e)] + e1[a0] + e2[a1])
__global__ void __launch_bounds__(256) k_agg(const float* __restrict__ e1l,
                                             const float* __restrict__ e2l) {
    __shared__ float4 se[10 * DIM4];   // 6 rows e1 + 4 rows e2
    int tid = threadIdx.x;
    for (int i = tid; i < 10 * DIM4; i += 256) {
        const float* src = (i < 6 * DIM4) ? (e1l + i * 4) : (e2l + (i - 6 * DIM4) * 4);
        se[i] = *(const float4*)src;
    }
    __syncthreads();
    int warp = tid >> 5, lane = tid & 31;
    int v = blockIdx.x * 8 + warp;
    if (v >= N_NODES) return;
    int s0 = g_row[v], s1 = g_row[v + 1];
    float4 acc = make_float4(0.f, 0.f, 0.f, 0.f);
    for (int e = s0; e < s1; e++) {
        int s  = g_csr_src[e];
        int at = g_csr_ea[e];
        float4 hv = ((const float4*)g_h)[s * DIM4 + lane];
        float4 t1 = se[(at & 7) * DIM4 + lane];
        float4 t2 = se[6 * DIM4 + (at >> 3) * DIM4 + lane];
        acc.x += hv.x + t1.x + t2.x;
        acc.y += hv.y + t1.y + t2.y;
        acc.z += hv.z + t1.z + t2.z;
        acc.w += hv.w + t1.w + t2.w;
    }
    ((float4*)g_agg)[v * DIM4 + lane] = acc;
}

// C[M,Nc] = (relu?)(A[M,K] @ B[K,Nc] + bias) ; BM=BN=128, BK=8, 8x8 per thread
__global__ void __launch_bounds__(256) k_sgemm(int M, int Nc, int K,
                                               const float* __restrict__ A,
                                               const float* __restrict__ B,
                                               const float* __restrict__ bias,
                                               float* __restrict__ C, int relu) {
    __shared__ float As[8][128];
    __shared__ float Bs[8][128];
    const int tid  = threadIdx.x;
    const int tCol = tid & 15;
    const int tRow = tid >> 4;
    const int irA = tid >> 1, icA = (tid & 1) * 4;
    const int irB = tid >> 5, icB = (tid & 31) * 4;
    const int rowBase = blockIdx.y * 128;
    const float* Ab = A + (size_t)rowBase * K;
    const float* Bb = B + blockIdx.x * 128;

    float res[8][8];
#pragma unroll
    for (int i = 0; i < 8; i++)
#pragma unroll
        for (int j = 0; j < 8; j++) res[i][j] = 0.f;

    for (int k0 = 0; k0 < K; k0 += 8) {
        float4 a4 = make_float4(0.f, 0.f, 0.f, 0.f);
        if (rowBase + irA < M)
            a4 = *(const float4*)(Ab + (size_t)irA * K + k0 + icA);
        As[icA + 0][irA] = a4.x;
        As[icA + 1][irA] = a4.y;
        As[icA + 2][irA] = a4.z;
        As[icA + 3][irA] = a4.w;
        *(float4*)&Bs[irB][icB] = *(const float4*)(Bb + (size_t)(k0 + irB) * Nc + icB);
        __syncthreads();
#pragma unroll
        for (int k = 0; k < 8; k++) {
            float4 m0 = *(float4*)&As[k][tRow * 8];
            float4 m1 = *(float4*)&As[k][tRow * 8 + 4];
            float4 n0 = *(float4*)&Bs[k][tCol * 8];
            float4 n1 = *(float4*)&Bs[k][tCol * 8 + 4];
            float rm[8] = {m0.x, m0.y, m0.z, m0.w, m1.x, m1.y, m1.z, m1.w};
            float rn[8] = {n0.x, n0.y, n0.z, n0.w, n1.x, n1.y, n1.z, n1.w};
#pragma unroll
            for (int i = 0; i < 8; i++)
#pragma unroll
                for (int j = 0; j < 8; j++) res[i][j] += rm[i] * rn[j];
        }
        __syncthreads();
    }

    int colBase = blockIdx.x * 128 + tCol * 8;
    float bl[8];
#pragma unroll
    for (int j = 0; j < 8; j++) bl[j] = bias[colBase + j];
#pragma unroll
    for (int i = 0; i < 8; i++) {
        int row = rowBase + tRow * 8 + i;
        if (row < M) {
            float o[8];
#pragma unroll
            for (int j = 0; j < 8; j++) {
                o[j] = res[i][j] + bl[j];
                if (relu) o[j] = fmaxf(o[j], 0.f);
            }
            *(float4*)(C + (size_t)row * Nc + colBase)     = make_float4(o[0], o[1], o[2], o[3]);
            *(float4*)(C + (size_t)row * Nc + colBase + 4) = make_float4(o[4], o[5], o[6], o[7]);
        }
    }
}

__global__ void k_zero_stats() {
    int i = threadIdx.x;
    if (i < 2 * DIM) g_stats[i] = 0.f;
}

__global__ void k_stats(const float* __restrict__ h2) {
    int c = threadIdx.x;   // 128 threads
    float s = 0.f, ss = 0.f;
    for (int r = blockIdx.x; r < N_NODES; r += gridDim.x) {
        float v = h2[(size_t)r * DIM + c];
        s += v;
        ss += v * v;
    }
    atomicAdd(&g_stats[c], s);
    atomicAdd(&g_stats[DIM + c], ss);
}

__global__ void k_bn(const float* __restrict__ h2,
                     const float* __restrict__ gamma,
                     const float* __restrict__ beta,
                     float* __restrict__ out, int relu) {
    __shared__ float sc[DIM], sh[DIM];
    int tid = threadIdx.x;
    if (tid < DIM) {
        float mu  = g_stats[tid] * (1.0f / N_NODES);
        float var = g_stats[DIM + tid] * (1.0f / N_NODES) - mu * mu;
        float s = gamma[tid] * rsqrtf(var + BN_EPS);
        sc[tid] = s;
        sh[tid] = beta[tid] - mu * s;
    }
    __syncthreads();
    int i = blockIdx.x * blockDim.x + tid;
    if (i >= N_NODES * DIM4) return;
    int c = (i & 31) * 4;
    float4 v = ((const float4*)h2)[i];
    v.x = v.x * sc[c + 0] + sh[c + 0];
    v.y = v.y * sc[c + 1] + sh[c + 1];
    v.z = v.z * sc[c + 2] + sh[c + 2];
    v.w = v.w * sc[c + 3] + sh[c + 3];
    if (relu) {
        v.x = fmaxf(v.x, 0.f); v.y = fmaxf(v.y, 0.f);
        v.z = fmaxf(v.z, 0.f); v.w = fmaxf(v.w, 0.f);
    }
    ((float4*)out)[i] = v;
}

// ---------------- launch ----------------
extern "C" void kernel_launch(void* const* d_in, const int* in_sizes, int n_in,
                              void* d_out, int out_size) {
    const int*   x     = (const int*)d_in[0];
    const int*   ei    = (const int*)d_in[1];
    const int*   ea    = (const int*)d_in[2];
    const float* atom  = (const float*)d_in[3];
    const float* chir  = (const float*)d_in[4];
    const float* hyb   = (const float*)d_in[5];
    const float* e1    = (const float*)d_in[6];
    const float* e2    = (const float*)d_in[7];
    const float* W1    = (const float*)d_in[8];
    const float* b1    = (const float*)d_in[9];
    const float* W2    = (const float*)d_in[10];
    const float* b2    = (const float*)d_in[11];
    const float* gamma = (const float*)d_in[12];
    const float* beta  = (const float*)d_in[13];
    float* out = (float*)d_out;

    float *pAgg, *pMid, *pH;
    cudaGetSymbolAddress((void**)&pAgg, g_agg);
    cudaGetSymbolAddress((void**)&pMid, g_mid);
    cudaGetSymbolAddress((void**)&pH,   g_h);

    const int TPB = 256;
    int nbE = (N_EDGES + TPB - 1) / TPB;
    int nbN = (N_NODES + TPB - 1) / TPB;
    int nbF4 = (N_NODES * DIM4) / TPB;        // 6250 exact

    k_init_h<<<nbF4, TPB>>>(x, atom, chir, hyb);
    k_zero_counts<<<nbN, TPB>>>();
    k_hist<<<nbE, TPB>>>(ei);
    int scanBlocks = (N_NODES + 1023) / 1024;  // 49
    k_scan1<<<scanBlocks, 1024>>>();
    k_scan2<<<1, 64>>>(scanBlocks);
    k_scan3<<<nbN, TPB>>>();
    k_scatter<<<nbE, TPB>>>(ei, ea);

    int gemmRows = (N_NODES + 127) / 128;      // 391
    for (int l = 0; l < NLAYER; l++) {
        k_agg<<<(N_NODES + 7) / 8, 256>>>(e1 + (size_t)l * 6 * DIM,
                                          e2 + (size_t)l * 4 * DIM);
        // mid = relu(agg @ W1 + b1)   [N, 256]
        k_sgemm<<<dim3(2, gemmRows), 256>>>(N_NODES, 2 * DIM, DIM,
                                            pAgg, W1 + (size_t)l * DIM * 2 * DIM,
                                            b1 + (size_t)l * 2 * DIM, pMid, 1);
        // h2 = mid @ W2 + b2          [N, 128]  (written back into g_agg)
        k_sgemm<<<dim3(1, gemmRows), 256>>>(N_NODES, DIM, 2 * DIM,
                                            pMid, W2 + (size_t)l * 2 * DIM * DIM,
                                            b2 + (size_t)l * DIM, pAgg, 0);
        k_zero_stats<<<1, 256>>>();
        k_stats<<<512, 128>>>(pAgg);
        int last = (l == NLAYER - 1);
        k_bn<<<nbF4, TPB>>>(pAgg, gamma + (size_t)l * DIM, beta + (size_t)l * DIM,
                            last ? out : pH, last ? 0 : 1);
    }
}

// round 3
// speedup vs baseline: 2.6519x; 2.6519x over previous
#include <cuda_runtime.h>
#include <cstdint>
#include <math.h>

#define N_NODES 50000
#define N_EDGES 600000
#define DIM     128
#define DIM4    32
#define NLAYER  5
#define BN_EPS  1e-5f

// ---------------- device scratch (no allocs allowed) ----------------
__device__ float g_h  [N_NODES * DIM];
__device__ float g_agg[N_NODES * DIM];
__device__ float g_mid[N_NODES * 2 * DIM];
__device__ int   g_counts[N_NODES];
__device__ int   g_row[N_NODES + 1];
__device__ int   g_cursor[N_NODES];
__device__ int   g_bsums[64];
__device__ int   g_csr_src[N_EDGES];
__device__ int   g_csr_ea [N_EDGES];
__device__ float g_stats[2 * DIM];

// ---------------- helpers ----------------
__device__ __forceinline__ uint32_t smem_u32(const void* p) {
    uint32_t a;
    asm("{ .reg .u64 t; cvta.to.shared.u64 t, %1; cvt.u32.u64 %0, t; }"
        : "=r"(a) : "l"(p));
    return a;
}

// hi = top 16 bits of fp32 (truncated bf16); pack two -> bf16x2 (elem0 in low half)
__device__ __forceinline__ uint32_t pack_hi(float a, float b) {
    return __byte_perm(__float_as_uint(a), __float_as_uint(b), 0x7632);
}
// lo = bf16(v - hi) for two elems; low half = elem0
__device__ __forceinline__ uint32_t pack_lo(float a, float b) {
    float ra = a - __uint_as_float(__float_as_uint(a) & 0xFFFF0000u);
    float rb = b - __uint_as_float(__float_as_uint(b) & 0xFFFF0000u);
    uint32_t r;
    asm("cvt.rn.bf16x2.f32 %0, %1, %2;" : "=r"(r) : "f"(rb), "f"(ra));
    return r;
}

__device__ __forceinline__ void ldsm4(uint32_t* r, uint32_t addr) {
    asm volatile("ldmatrix.sync.aligned.m8n8.x4.shared.b16 {%0,%1,%2,%3}, [%4];"
        : "=r"(r[0]), "=r"(r[1]), "=r"(r[2]), "=r"(r[3]) : "r"(addr));
}
__device__ __forceinline__ void ldsm2t(uint32_t* r, uint32_t addr) {
    asm volatile("ldmatrix.sync.aligned.m8n8.x2.trans.shared.b16 {%0,%1}, [%2];"
        : "=r"(r[0]), "=r"(r[1]) : "r"(addr));
}
__device__ __forceinline__ void mma_bf16(float* c, const uint32_t* a, const uint32_t* b) {
    asm volatile("mma.sync.aligned.m16n8k16.row.col.f32.bf16.bf16.f32 "
        "{%0,%1,%2,%3}, {%4,%5,%6,%7}, {%8,%9}, {%0,%1,%2,%3};"
        : "+f"(c[0]), "+f"(c[1]), "+f"(c[2]), "+f"(c[3])
        : "r"(a[0]), "r"(a[1]), "r"(a[2]), "r"(a[3]), "r"(b[0]), "r"(b[1]));
}

// ---------------- setup kernels ----------------
__global__ void k_init_h(const int* __restrict__ x,
                         const float* __restrict__ ae,
                         const float* __restrict__ ce,
                         const float* __restrict__ he) {
    int i = blockIdx.x * blockDim.x + threadIdx.x;
    if (i >= N_NODES * DIM4) return;
    int r = i >> 5, q = i & 31;
    int a = x[r * 3 + 0];
    int c = x[r * 3 + 1];
    int h = x[r * 3 + 2];
    float4 v  = ((const float4*)ae)[a * DIM4 + q];
    float4 v2 = ((const float4*)ce)[c * DIM4 + q];
    float4 v3 = ((const float4*)he)[h * DIM4 + q];
    v.x += v2.x + v3.x; v.y += v2.y + v3.y;
    v.z += v2.z + v3.z; v.w += v2.w + v3.w;
    ((float4*)g_h)[i] = v;
}

__global__ void k_zero_counts() {
    int i = blockIdx.x * blockDim.x + threadIdx.x;
    if (i < N_NODES) g_counts[i] = 0;
}

__global__ void k_hist(const int* __restrict__ ei) {
    int e = blockIdx.x * blockDim.x + threadIdx.x;
    if (e >= N_EDGES) return;
    atomicAdd(&g_counts[ei[N_EDGES + e]], 1);
}

__global__ void k_scan1() {
    __shared__ int sm[1024];
    int t = threadIdx.x;
    int gid = blockIdx.x * 1024 + t;
    int v = (gid < N_NODES) ? g_counts[gid] : 0;
    sm[t] = v;
    __syncthreads();
    for (int off = 1; off < 1024; off <<= 1) {
        int add = (t >= off) ? sm[t - off] : 0;
        __syncthreads();
        sm[t] += add;
        __syncthreads();
    }
    if (gid < N_NODES) g_row[gid] = sm[t] - v;
    if (t == 1023) g_bsums[blockIdx.x] = sm[1023];
}

__global__ void k_scan2(int nb) {
    __shared__ int sm[64];
    int t = threadIdx.x;
    int v = (t < nb) ? g_bsums[t] : 0;
    sm[t] = v;
    __syncthreads();
    for (int off = 1; off < 64; off <<= 1) {
        int add = (t >= off) ? sm[t - off] : 0;
        __syncthreads();
        sm[t] += add;
        __syncthreads();
    }
    if (t < nb) g_bsums[t] = sm[t] - v;
}

__global__ void k_scan3() {
    int gid = blockIdx.x * blockDim.x + threadIdx.x;
    if (gid < N_NODES) {
        int r = g_row[gid] + g_bsums[gid >> 10];
        g_row[gid] = r;
        g_cursor[gid] = r;
    }
    if (gid == 0) g_row[N_NODES] = N_EDGES;
}

__global__ void k_scatter(const int* __restrict__ ei, const int* __restrict__ ea) {
    int e = blockIdx.x * blockDim.x + threadIdx.x;
    if (e >= N_EDGES) return;
    int d = ei[N_EDGES + e];
    int p = atomicAdd(&g_cursor[d], 1);
    g_csr_src[p] = ei[e];
    g_csr_ea[p]  = ea[2 * e] + (ea[2 * e + 1] << 3);
}

__global__ void __launch_bounds__(256) k_agg(const float* __restrict__ e1l,
                                             const float* __restrict__ e2l) {
    __shared__ float4 se[10 * DIM4];
    int tid = threadIdx.x;
    for (int i = tid; i < 10 * DIM4; i += 256) {
        const float* src = (i < 6 * DIM4) ? (e1l + i * 4) : (e2l + (i - 6 * DIM4) * 4);
        se[i] = *(const float4*)src;
    }
    __syncthreads();
    int warp = tid >> 5, lane = tid & 31;
    int v = blockIdx.x * 8 + warp;
    if (v >= N_NODES) return;
    int s0 = g_row[v], s1 = g_row[v + 1];
    float4 acc = make_float4(0.f, 0.f, 0.f, 0.f);
    for (int e = s0; e < s1; e++) {
        int s  = g_csr_src[e];
        int at = g_csr_ea[e];
        float4 hv = ((const float4*)g_h)[s * DIM4 + lane];
        float4 t1 = se[(at & 7) * DIM4 + lane];
        float4 t2 = se[6 * DIM4 + (at >> 3) * DIM4 + lane];
        acc.x += hv.x + t1.x + t2.x;
        acc.y += hv.y + t1.y + t2.y;
        acc.z += hv.z + t1.z + t2.z;
        acc.w += hv.w + t1.w + t2.w;
    }
    ((float4*)g_agg)[v * DIM4 + lane] = acc;
}

// ---------------- split-bf16 HMMA GEMM ----------------
// C[M,Nc] = (relu?)(A[M,K] @ B[K,Nc] + bias); K in {128,256}, Nc multiple of 128.
// grid (Nc/128, ceil(M/128)), 256 threads, dyn smem 139264B.
// smem planes (bf16, row pad +8): As_hi/As_lo [128][136], Bs_hi/Bs_lo [128][136]
#define LDT 136
#define PLANE (128 * LDT * 2)          // bytes per plane (34816)

__global__ void __launch_bounds__(256, 1) k_hmma(
    int M, int Nc, int K,
    const float* __restrict__ A, const float* __restrict__ B,
    const float* __restrict__ bias, float* __restrict__ C, int relu) {
    extern __shared__ char smem[];
    const uint32_t sb = smem_u32(smem);
    const uint32_t AH = sb, AL = sb + PLANE, BH = sb + 2 * PLANE, BL = sb + 3 * PLANE;
    char* pAH = smem;
    char* pAL = smem + PLANE;
    char* pBH = smem + 2 * PLANE;
    char* pBL = smem + 3 * PLANE;

    const int tid = threadIdx.x, wid = tid >> 5, lane = tid & 31;
    const int wm = wid >> 2;            // 0..1  (64-row warp stripe)
    const int wn = wid & 3;             // 0..3  (32-col warp stripe)
    const int rowBase = blockIdx.y << 7;
    const int colBase = blockIdx.x << 7;

    float acc[4][4][4];
#pragma unroll
    for (int i = 0; i < 4; i++)
#pragma unroll
        for (int j = 0; j < 4; j++)
#pragma unroll
            for (int k = 0; k < 4; k++) acc[i][j][k] = 0.f;

    const int nCh = K >> 7;
    for (int ch = 0; ch < nCh; ch++) {
        const int kBase = ch << 7;
        if (ch) __syncthreads();
        // ---- fill A (128 rows x 128 k-cols) ----
#pragma unroll
        for (int it = 0; it < 16; it++) {
            int g = tid + it * 256;                 // 0..4095
            int r = g >> 5, c4 = (g & 31) << 2;
            float4 v = make_float4(0.f, 0.f, 0.f, 0.f);
            if (rowBase + r < M)
                v = *(const float4*)(A + (size_t)(rowBase + r) * K + kBase + c4);
            uint2 hi, lo;
            hi.x = pack_hi(v.x, v.y); hi.y = pack_hi(v.z, v.w);
            lo.x = pack_lo(v.x, v.y); lo.y = pack_lo(v.z, v.w);
            int off = (r * LDT + c4) * 2;
            *(uint2*)(pAH + off) = hi;
            *(uint2*)(pAL + off) = lo;
        }
        // ---- fill B (128 k-rows x 128 n-cols) ----
#pragma unroll
        for (int it = 0; it < 16; it++) {
            int g = tid + it * 256;
            int r = g >> 5, c4 = (g & 31) << 2;
            float4 v = *(const float4*)(B + (size_t)(kBase + r) * Nc + colBase + c4);
            uint2 hi, lo;
            hi.x = pack_hi(v.x, v.y); hi.y = pack_hi(v.z, v.w);
            lo.x = pack_lo(v.x, v.y); lo.y = pack_lo(v.z, v.w);
            int off = (r * LDT + c4) * 2;
            *(uint2*)(pBH + off) = hi;
            *(uint2*)(pBL + off) = lo;
        }
        __syncthreads();

        // ---- compute: 8 k16 steps ----
        const int arow = wm * 64 + (lane & 15);
        const int acolSel = (lane >> 4) << 3;
        const int brow = lane & 15;
#pragma unroll
        for (int kk = 0; kk < 8; kk++) {
            uint32_t ah[4][4], al[4][4], bh[4][2], bl[4][2];
            int acol = kk * 16 + acolSel;
#pragma unroll
            for (int mi = 0; mi < 4; mi++) {
                uint32_t ao = (uint32_t)(((arow + mi * 16) * LDT + acol) * 2);
                ldsm4(ah[mi], AH + ao);
                ldsm4(al[mi], AL + ao);
            }
#pragma unroll
            for (int ni = 0; ni < 4; ni++) {
                uint32_t bo = (uint32_t)(((kk * 16 + brow) * LDT + wn * 32 + ni * 8) * 2);
                ldsm2t(bh[ni], BH + bo);
                ldsm2t(bl[ni], BL + bo);
            }
#pragma unroll
            for (int mi = 0; mi < 4; mi++)
#pragma unroll
                for (int ni = 0; ni < 4; ni++) {
                    mma_bf16(acc[mi][ni], ah[mi], bh[ni]);
                    mma_bf16(acc[mi][ni], ah[mi], bl[ni]);
                    mma_bf16(acc[mi][ni], al[mi], bh[ni]);
                }
        }
    }

    // ---- epilogue ----
    const int rBase = rowBase + wm * 64 + (lane >> 2);
    const int cBase = colBase + wn * 32 + (lane & 3) * 2;
#pragma unroll
    for (int mi = 0; mi < 4; mi++) {
#pragma unroll
        for (int h = 0; h < 2; h++) {
            int row = rBase + mi * 16 + h * 8;
            if (row < M) {
#pragma unroll
                for (int ni = 0; ni < 4; ni++) {
                    int col = cBase + ni * 8;
                    float2 o;
                    o.x = acc[mi][ni][2 * h + 0] + bias[col];
                    o.y = acc[mi][ni][2 * h + 1] + bias[col + 1];
                    if (relu) { o.x = fmaxf(o.x, 0.f); o.y = fmaxf(o.y, 0.f); }
                    *(float2*)(C + (size_t)row * Nc + col) = o;
                }
            }
        }
    }
}

// ---------------- BN kernels ----------------
__global__ void k_zero_stats() {
    int i = threadIdx.x;
    if (i < 2 * DIM) g_stats[i] = 0.f;
}

__global__ void k_stats(const float* __restrict__ h2) {
    int c = threadIdx.x;
    float s = 0.f, ss = 0.f;
    for (int r = blockIdx.x; r < N_NODES; r += gridDim.x) {
        float v = h2[(size_t)r * DIM + c];
        s += v;
        ss += v * v;
    }
    atomicAdd(&g_stats[c], s);
    atomicAdd(&g_stats[DIM + c], ss);
}

__global__ void k_bn(const float* __restrict__ h2,
                     const float* __restrict__ gamma,
                     const float* __restrict__ beta,
                     float* __restrict__ out, int relu) {
    __shared__ float sc[DIM], sh[DIM];
    int tid = threadIdx.x;
    if (tid < DIM) {
        float mu  = g_stats[tid] * (1.0f / N_NODES);
        float var = g_stats[DIM + tid] * (1.0f / N_NODES) - mu * mu;
        float s = gamma[tid] * rsqrtf(var + BN_EPS);
        sc[tid] = s;
        sh[tid] = beta[tid] - mu * s;
    }
    __syncthreads();
    int i = blockIdx.x * blockDim.x + tid;
    if (i >= N_NODES * DIM4) return;
    int c = (i & 31) * 4;
    float4 v = ((const float4*)h2)[i];
    v.x = v.x * sc[c + 0] + sh[c + 0];
    v.y = v.y * sc[c + 1] + sh[c + 1];
    v.z = v.z * sc[c + 2] + sh[c + 2];
    v.w = v.w * sc[c + 3] + sh[c + 3];
    if (relu) {
        v.x = fmaxf(v.x, 0.f); v.y = fmaxf(v.y, 0.f);
        v.z = fmaxf(v.z, 0.f); v.w = fmaxf(v.w, 0.f);
    }
    ((float4*)out)[i] = v;
}

// ---------------- launch ----------------
extern "C" void kernel_launch(void* const* d_in, const int* in_sizes, int n_in,
                              void* d_out, int out_size) {
    const int*   x     = (const int*)d_in[0];
    const int*   ei    = (const int*)d_in[1];
    const int*   ea    = (const int*)d_in[2];
    const float* atom  = (const float*)d_in[3];
    const float* chir  = (const float*)d_in[4];
    const float* hyb   = (const float*)d_in[5];
    const float* e1    = (const float*)d_in[6];
    const float* e2    = (const float*)d_in[7];
    const float* W1    = (const float*)d_in[8];
    const float* b1    = (const float*)d_in[9];
    const float* W2    = (const float*)d_in[10];
    const float* b2    = (const float*)d_in[11];
    const float* gamma = (const float*)d_in[12];
    const float* beta  = (const float*)d_in[13];
    float* out = (float*)d_out;

    float *pAgg, *pMid, *pH;
    cudaGetSymbolAddress((void**)&pAgg, g_agg);
    cudaGetSymbolAddress((void**)&pMid, g_mid);
    cudaGetSymbolAddress((void**)&pH,   g_h);

    const int SMEM_MMA = 4 * PLANE;   // 139264
    cudaFuncSetAttribute(k_hmma, cudaFuncAttributeMaxDynamicSharedMemorySize, SMEM_MMA);

    const int TPB = 256;
    int nbE = (N_EDGES + TPB - 1) / TPB;
    int nbN = (N_NODES + TPB - 1) / TPB;
    int nbF4 = (N_NODES * DIM4) / TPB;

    k_init_h<<<nbF4, TPB>>>(x, atom, chir, hyb);
    k_zero_counts<<<nbN, TPB>>>();
    k_hist<<<nbE, TPB>>>(ei);
    int scanBlocks = (N_NODES + 1023) / 1024;
    k_scan1<<<scanBlocks, 1024>>>();
    k_scan2<<<1, 64>>>(scanBlocks);
    k_scan3<<<nbN, TPB>>>();
    k_scatter<<<nbE, TPB>>>(ei, ea);

    int gemmRows = (N_NODES + 127) / 128;   // 391
    for (int l = 0; l < NLAYER; l++) {
        k_agg<<<(N_NODES + 7) / 8, 256>>>(e1 + (size_t)l * 6 * DIM,
                                          e2 + (size_t)l * 4 * DIM);
        // mid = relu(agg @ W1 + b1)   [N, 256]
        k_hmma<<<dim3(2, gemmRows), 256, SMEM_MMA>>>(
            N_NODES, 2 * DIM, DIM, pAgg,
            W1 + (size_t)l * DIM * 2 * DIM, b1 + (size_t)l * 2 * DIM, pMid, 1);
        // h2 = mid @ W2 + b2          [N, 128]
        k_hmma<<<dim3(1, gemmRows), 256, SMEM_MMA>>>(
            N_NODES, DIM, 2 * DIM, pMid,
            W2 + (size_t)l * 2 * DIM * DIM, b2 + (size_t)l * DIM, pAgg, 0);
        k_zero_stats<<<1, 256>>>();
        k_stats<<<512, 128>>>(pAgg);
        int last = (l == NLAYER - 1);
        k_bn<<<nbF4, TPB>>>(pAgg, gamma + (size_t)l * DIM, beta + (size_t)l * DIM,
                            last ? out : pH, last ? 0 : 1);
    }
}